// round 12
// baseline (speedup 1.0000x reference)
#include <cuda_runtime.h>
#include <cuda_fp16.h>
#include <math.h>

#define N_   131072
#define D_   64
#define K_   2048
#define RPB  128              // rows per block
#define CPC  128              // codes per chunk
#define NCH  (K_ / CPC)       // 16 chunks
#define XSS  132              // xs fp32 stride
#define XHS  132              // xs_h u32 stride
#define TPB  256
#define GRID (N_ / RPB)       // 1024 blocks
#define MARG    0.075f        // >= 2x rigorous fp16 dot error bound (0.034)
#define MARG_FX 2468
#define QTH  24               // per-thread queue capacity

typedef unsigned int u32;
typedef unsigned long long u64;

// Device scratch (no allocations allowed)
__device__ __align__(16) float g_en  [K_ * D_];   // fp32 codebook (exact path)
__device__ __align__(16) float g_see [K_];
__device__ __align__(16) u32   g_enh [K_ * 32];   // fp16x2 {e[2dp],e[2dp+1]}: [ch][dp][c]
__device__ float g_part[GRID];

// ---- smem byte offsets ----
#define OFF_XS   0            // 33792  xs fp32 [64][132]
#define OFF_XSH  33792        // 16896  xs_h u32 [32][132] fp16 {x2dp,x2dp+1}
#define OFF_B0   50688        // 16384  B buf0 u32 [32][128]
#define OFF_B1   67072        // 16384  B buf1
#define OFF_SXX  83456        // 512
#define OFF_RB   83968        // 1024   u64[128] packed (valbits, code)
#define OFF_Q    84992        // 24576  queues, interleaved [i][tid]
#define DYNSMEM  109568

// ---------------- helpers ----------------
__device__ __forceinline__ u32 smem_u32(const void* p) {
    u32 a; asm("{ .reg .u64 t; cvta.to.shared.u64 t, %1; cvt.u32.u64 %0, t; }" : "=r"(a) : "l"(p));
    return a;
}
__device__ __forceinline__ void cp16(u32 dst, const void* src) {
    asm volatile("cp.async.cg.shared.global [%0], [%1], 16;" :: "r"(dst), "l"(src) : "memory");
}
__device__ __forceinline__ void cp_commit() { asm volatile("cp.async.commit_group;" ::: "memory"); }
template<int W> __device__ __forceinline__ void cp_wait() {
    asm volatile("cp.async.wait_group %0;" :: "n"(W) : "memory");
}
__device__ __forceinline__ u32 hfma2(u32 a, u32 b, u32 c) {
    u32 d; asm("fma.rn.f16x2 %0, %1, %2, %3;" : "=r"(d) : "r"(a), "r"(b), "r"(c)); return d;
}
__device__ __forceinline__ u32 fix16(float v) {
    float c = fminf(fmaxf(fmaf(v, 32767.f, 32768.f), 0.f), 65535.f);
    return (u32)c;
}
// exact fp32 rescore (identical formula/order to passing kernels) + atomicMin key
__device__ __noinline__ void exact_rescore(const float* xs, const float* sxx,
                                           u64* rbest, int row, int code) {
    float dot = 0.f;
    const float* er = g_en + code * 64;
    #pragma unroll
    for (int d = 0; d < 64; d++) dot = fmaf(xs[d * XSS + row], er[d], dot);
    float val = fmaf(-2.0f, dot, sxx[row] + g_see[code]);
    u32 vb = __float_as_uint(val);
    vb = (vb & 0x80000000u) ? ~vb : (vb | 0x80000000u);     // order-preserving
    u64 key = ((u64)vb << 32) | (u32)code;
    atomicMin(rbest + row, key);                            // min val, tie -> min idx
}

// ---------------------------------------------------------------------------
// Kernel 1: normalize embeddings -> g_en, g_see, g_enh (fp16 d-pairs).
// One warp per code row; lane dp builds {e[2dp], e[2dp+1]}.
// ---------------------------------------------------------------------------
__global__ void vq_norm_emb(const float* __restrict__ emb) {
    int w    = (blockIdx.x * blockDim.x + threadIdx.x) >> 5;
    int lane = threadIdx.x & 31;
    if (w >= K_) return;
    float v0 = emb[w * 64 + lane];
    float v1 = emb[w * 64 + lane + 32];
    float s  = v0 * v0 + v1 * v1;
    #pragma unroll
    for (int o = 16; o > 0; o >>= 1) s += __shfl_xor_sync(0xffffffffu, s, o);
    float inv = 1.0f / fmaxf(sqrtf(s), 1e-12f);
    float e0 = v0 * inv, e1 = v1 * inv;
    g_en[w * 64 + lane]      = e0;
    g_en[w * 64 + lane + 32] = e1;
    float t = e0 * e0 + e1 * e1;   // see from ROUNDED values (matches reference)
    #pragma unroll
    for (int o = 16; o > 0; o >>= 1) t += __shfl_xor_sync(0xffffffffu, t, o);
    if (lane == 0) g_see[w] = t;
    // lane dp: pair {e[2dp], e[2dp+1]}; dims 0..31 in e0, 32..63 in e1
    int sl = (2 * lane) & 31;
    float a0 = __shfl_sync(0xffffffffu, e0, sl);
    float a1 = __shfl_sync(0xffffffffu, e0, sl + 1);
    float b0 = __shfl_sync(0xffffffffu, e1, sl);
    float b1 = __shfl_sync(0xffffffffu, e1, sl + 1);
    float va = (lane < 16) ? a0 : b0;
    float vb = (lane < 16) ? a1 : b1;
    __half2 h = __floats2half2_rn(va, vb);
    int ch = w >> 7, c = w & 127;
    g_enh[ch * 4096 + lane * 128 + c] = *(u32*)&h;
}

// ---------------------------------------------------------------------------
// Kernel 2: HFMA2 fp16 screening (d-parity packed) + exact fp32 rescore.
// 256 threads; thread tile 8 rows (ty) x 8 codes (tx); 16 chunks of 128.
// ---------------------------------------------------------------------------
extern __shared__ char smem_[];

__global__ void __launch_bounds__(TPB, 1)
vq_main(const float* __restrict__ x, float* __restrict__ out, int out_size) {
    char* base = smem_;
    float* xs   = (float*)(base + OFF_XS);
    u32*   xsh  = (u32*)  (base + OFF_XSH);
    float* sxx  = (float*)(base + OFF_SXX);
    u64*   rbest= (u64*)  (base + OFF_RB);
    u32*   qbuf = (u32*)  (base + OFF_Q);     // entry i of thread t at [i*TPB + t]

    int tid = threadIdx.x;
    int tx  = tid & 15;            // code group (8 codes)
    int ty  = tid >> 4;            // row group (8 rows)
    int rowbase = blockIdx.x * RPB;

    if (tid < RPB) rbest[tid] = 0xFFFFFFFFFFFFFFFFull;

    // prefetch B chunk 0 (16KB contiguous)
    {
        u32 dst = smem_u32(base + OFF_B0);
        const char* src = (const char*)g_enh;
        #pragma unroll
        for (int i = 0; i < 4; i++) {
            int idx = i * TPB + tid;
            cp16(dst + (u32)idx * 16u, src + (size_t)idx * 16);
        }
        cp_commit();
    }

    // load x tile, transposed
    #pragma unroll
    for (int i = 0; i < 32; i++) {
        int e = i * TPB + tid;
        int r = e >> 6, d = e & 63;
        xs[d * XSS + r] = x[(rowbase + r) * 64 + d];
    }
    __syncthreads();

    // normalize rows; sxx
    if (tid < RPB) {
        float s = 0.f;
        #pragma unroll
        for (int d = 0; d < 64; d++) { float v = xs[d * XSS + tid]; s += v * v; }
        float inv = 1.0f / fmaxf(sqrtf(s), 1e-12f);
        float s2 = 0.f;
        #pragma unroll
        for (int d = 0; d < 64; d++) {
            float v = xs[d * XSS + tid] * inv;
            xs[d * XSS + tid] = v;
            s2 += v * v;
        }
        sxx[tid] = s2;
    }
    __syncthreads();

    // build fp16 A pairs: xsh[dp][r] = {xn[2dp], xn[2dp+1]}
    #pragma unroll
    for (int i = 0; i < 16; i++) {
        int e = i * TPB + tid;
        int dp = e >> 7, r = e & 127;
        __half2 h = __floats2half2_rn(xs[(2 * dp) * XSS + r],
                                      (xs[(2 * dp + 1) * XSS + r]));
        xsh[dp * XHS + r] = *(u32*)&h;
    }
    __syncthreads();

    float rm[8];
    #pragma unroll
    for (int j = 0; j < 8; j++) rm[j] = -1e30f;
    int qn = 0;

    for (int ch = 0; ch < NCH; ch++) {
        if (ch + 1 < NCH) {
            u32 dst = smem_u32(base + (((ch + 1) & 1) ? OFF_B1 : OFF_B0));
            const char* src = (const char*)g_enh + (size_t)(ch + 1) * 16384;
            #pragma unroll
            for (int i = 0; i < 4; i++) {
                int idx = i * TPB + tid;
                cp16(dst + (u32)idx * 16u, src + (size_t)idx * 16);
            }
            cp_commit();
            cp_wait<1>();     // chunk ch landed
        } else {
            cp_wait<0>();
        }
        __syncthreads();

        const u32* eb = (const u32*)(base + ((ch & 1) ? OFF_B1 : OFF_B0));

        u32 acc[8][8];
        #pragma unroll
        for (int j = 0; j < 8; j++)
            #pragma unroll
            for (int i = 0; i < 8; i++) acc[j][i] = 0u;   // fp16x2 zero

        #pragma unroll 4
        for (int dp = 0; dp < 32; dp++) {
            uint4 A0 = *(const uint4*)(xsh + dp * XHS + ty * 8);
            uint4 A1 = *(const uint4*)(xsh + dp * XHS + ty * 8 + 4);
            u32 A[8] = {A0.x, A0.y, A0.z, A0.w, A1.x, A1.y, A1.z, A1.w};
            uint4 B0 = *(const uint4*)(eb + dp * 128 + tx * 8);
            uint4 B1 = *(const uint4*)(eb + dp * 128 + tx * 8 + 4);
            u32 B[8] = {B0.x, B0.y, B0.z, B0.w, B1.x, B1.y, B1.z, B1.w};
            #pragma unroll
            for (int j = 0; j < 8; j++)
                #pragma unroll
                for (int i = 0; i < 8; i++)
                    acc[j][i] = hfma2(A[j], B[i], acc[j][i]);
        }

        // screening epilogue: dot = lo + hi (d-parity halves), group-max path
        int cbase = ch * CPC + tx * 8;
        #pragma unroll
        for (int j = 0; j < 8; j++) {
            __half s[8];
            #pragma unroll
            for (int i = 0; i < 8; i++) {
                __half2 h = *(__half2*)&acc[j][i];
                s[i] = __hadd(__low2half(h), __high2half(h));
            }
            __half m = s[0];
            #pragma unroll
            for (int i = 1; i < 8; i++) m = __hmax(m, s[i]);
            float gm = __half2float(m);
            if (gm > rm[j] - MARG) {                 // rare slow path
                float th = fmaxf(rm[j], gm) - MARG;
                #pragma unroll
                for (int i = 0; i < 8; i++) {
                    float v = __half2float(s[i]);
                    if (v > th) {
                        int code = cbase + i;
                        if (qn >= QTH) {             // purge stale entries
                            int w2 = 0;
                            for (int q = 0; q < qn; q++) {
                                u32 e = qbuf[q * TPB + tid];
                                int jj = (e >> 11) & 7;
                                if ((e >> 16) + 8 >= fix16(rm[jj] - MARG))
                                    qbuf[w2++ * TPB + tid] = e;
                            }
                            qn = w2;
                        }
                        if (qn < QTH) {
                            qbuf[qn * TPB + tid] =
                                (fix16(v) << 16) | ((u32)j << 11) | (u32)code;
                            qn++;
                        } else {                     // guaranteed-correct fallback
                            exact_rescore(xs, sxx, rbest, ty * 8 + j, code);
                        }
                    }
                }
            }
            rm[j] = fmaxf(rm[j], gm);
        }
        __syncthreads();
    }

    // refilter queue vs final per-thread stream max; exact-rescore survivors
    for (int i = 0; i < qn; i++) {
        u32 e = qbuf[i * TPB + tid];
        int code = e & 2047;
        int j    = (e >> 11) & 7;
        if ((e >> 16) + MARG_FX >= fix16(rm[j]))
            exact_rescore(xs, sxx, rbest, ty * 8 + j, code);
    }
    __syncthreads();

    // ---- per-row final: quantized_st, idx, loss ----
    float lsum = 0.f;
    if (tid < RPB) {
        int bk = (int)(rbest[tid] & 2047u);
        float inv2 = 1.0f / fmaxf(sqrtf(g_see[bk]), 1e-12f);
        const float* erow = g_en + bk * 64;
        #pragma unroll
        for (int d = 0; d < 64; d++) {
            float xnv  = xs[d * XSS + tid];
            float qd   = erow[d] * inv2;
            float diff = qd - xnv;
            lsum += diff * diff;
            xs[d * XSS + tid] = xnv + diff;
        }
        if (out_size >= N_ * D_ + 1 + N_)
            out[N_ * D_ + 1 + rowbase + tid] = (float)bk;
    }
    __syncthreads();

    // coalesced store of quantized_st
    #pragma unroll
    for (int i = 0; i < 32; i++) {
        int e = i * TPB + tid;
        out[rowbase * 64 + e] = xs[(e & 63) * XSS + (e >> 6)];
    }

    // deterministic block loss reduction (queue space is dead now)
    float* red = (float*)(base + OFF_Q);
    if (tid < RPB) red[tid] = lsum;
    __syncthreads();
    for (int s = 64; s > 0; s >>= 1) {
        if (tid < s) red[tid] += red[tid + s];
        __syncthreads();
    }
    if (tid == 0) g_part[blockIdx.x] = red[0];
}

// ---------------------------------------------------------------------------
// Kernel 3: deterministic final loss reduction.
// loss = q_latent + 0.25*e_latent = 1.25 * mean((q - xn)^2)
// ---------------------------------------------------------------------------
__global__ void vq_final(float* __restrict__ out, int out_size) {
    __shared__ float sm[256];
    int tid = threadIdx.x;
    float s = g_part[tid] + g_part[tid + 256] + g_part[tid + 512] + g_part[tid + 768];
    sm[tid] = s;
    __syncthreads();
    for (int st = 128; st > 0; st >>= 1) {
        if (tid < st) sm[tid] += sm[tid + st];
        __syncthreads();
    }
    if (tid == 0 && out_size > N_ * D_)
        out[N_ * D_] = 1.25f * (sm[0] / (float)(N_ * D_));
}

// ---------------------------------------------------------------------------
extern "C" void kernel_launch(void* const* d_in, const int* in_sizes, int n_in,
                              void* d_out, int out_size) {
    const float* x;
    const float* emb;
    if (n_in >= 2 && in_sizes[0] >= in_sizes[1]) {
        x = (const float*)d_in[0]; emb = (const float*)d_in[1];
    } else {
        x = (const float*)d_in[1]; emb = (const float*)d_in[0];
    }

    cudaFuncSetAttribute(vq_main, cudaFuncAttributeMaxDynamicSharedMemorySize, DYNSMEM);

    vq_norm_emb<<<K_ / 8, 256>>>(emb);
    vq_main<<<GRID, TPB, DYNSMEM>>>(x, (float*)d_out, out_size);
    vq_final<<<1, 256>>>((float*)d_out, out_size);
}

// round 13
// speedup vs baseline: 52.8271x; 52.8271x over previous
#include <cuda_runtime.h>
#include <math.h>

// Problem constants (shapes fixed by setup_inputs)
#define N_   131072
#define D_   64
#define K_   2048
#define RPB  128              // rows per block
#define CPC  256              // codes per smem chunk
#define NCH  (K_ / CPC)       // 8 chunks
#define XSS  132              // padded xs stride (floats)
#define TPB  256
#define GRID (N_ / RPB)       // 1024 blocks

typedef unsigned long long ull;

// Device scratch (no allocations allowed)
__device__ __align__(16) float g_en  [K_ * D_];   // normalized codebook [k][d]
__device__ __align__(16) float g_ent [K_ * D_];   // chunk-transposed: [chunk][d][c]
__device__ __align__(16) float g_see [K_];        // sum(en^2) per code
__device__ float g_part[GRID];                    // per-block loss partials

// ---- f32x2 helpers (FFMA2 is only reachable via PTX fma.rn.f32x2) ----
__device__ __forceinline__ ull dup2(float v) {
    ull r; asm("mov.b64 %0, {%1, %1};" : "=l"(r) : "r"(__float_as_uint(v))); return r;
}
__device__ __forceinline__ ull fma2(ull a, ull b, ull c) {
    ull d; asm("fma.rn.f32x2 %0, %1, %2, %3;" : "=l"(d) : "l"(a), "l"(b), "l"(c)); return d;
}
__device__ __forceinline__ void unpack2(ull v, float& lo, float& hi) {
    asm("mov.b64 {%0, %1}, %2;" : "=f"(lo), "=f"(hi) : "l"(v));
}
__device__ __forceinline__ void cp16(unsigned dst, const void* src) {
    asm volatile("cp.async.cg.shared.global [%0], [%1], 16;" :: "r"(dst), "l"(src) : "memory");
}
__device__ __forceinline__ void cp_commit() {
    asm volatile("cp.async.commit_group;" ::: "memory");
}
template<int W> __device__ __forceinline__ void cp_wait() {
    asm volatile("cp.async.wait_group %0;" :: "n"(W) : "memory");
}

// ---------------------------------------------------------------------------
// Kernel 1: normalize embeddings -> row-major + chunk-transposed + see[k].
// One warp per code row (D=64 -> 2 elems/lane).
// ---------------------------------------------------------------------------
__global__ void vq_norm_emb(const float* __restrict__ emb) {
    int w    = (blockIdx.x * blockDim.x + threadIdx.x) >> 5;   // code index
    int lane = threadIdx.x & 31;
    if (w >= K_) return;
    float v0 = emb[w * 64 + lane];
    float v1 = emb[w * 64 + lane + 32];
    float s  = v0 * v0 + v1 * v1;
    #pragma unroll
    for (int o = 16; o > 0; o >>= 1) s += __shfl_xor_sync(0xffffffffu, s, o);
    float inv = 1.0f / fmaxf(sqrtf(s), 1e-12f);
    float e0 = v0 * inv, e1 = v1 * inv;
    g_en[w * 64 + lane]      = e0;
    g_en[w * 64 + lane + 32] = e1;
    float t = e0 * e0 + e1 * e1;   // see from ROUNDED values (matches reference)
    #pragma unroll
    for (int o = 16; o > 0; o >>= 1) t += __shfl_xor_sync(0xffffffffu, t, o);
    if (lane == 0) g_see[w] = t;
    int ch = w >> 8, c = w & (CPC - 1);
    g_ent[(ch * 64 + lane)      * CPC + c] = e0;
    g_ent[(ch * 64 + lane + 32) * CPC + c] = e1;
}

// ---------------------------------------------------------------------------
// Kernel 2: fused normalize(x) + argmin + quantized_st + idx + loss.
// Block: 128 rows x 2048 codes. Thread: 8 rows x 16 codes via f32x2 acc pairs.
// Double-buffered cp.async chunk loads (CPC=256 codes per chunk).
// ---------------------------------------------------------------------------
extern __shared__ float smem_[];

__global__ void __launch_bounds__(TPB, 1)
vq_main(const float* __restrict__ x, float* __restrict__ out, int out_size) {
    float* xs   = smem_;                          // [64][XSS]
    float* es0  = xs + 64 * XSS;                  // [64][CPC] buf 0
    float* es1  = es0 + 64 * CPC;                 // [64][CPC] buf 1
    float* sees = es1 + 64 * CPC;                 // [K_] all code see's

    int tid = threadIdx.x;
    int tx  = tid & 15;                  // code-pair group
    int ty  = tid >> 4;                  // row group (8 rows)
    int rowbase = blockIdx.x * RPB;

    unsigned es_u0 = (unsigned)__cvta_generic_to_shared(es0);
    unsigned es_u1 = (unsigned)__cvta_generic_to_shared(es1);

    // ---- prefetch chunk 0 (64KB) via cp.async ----
    {
        const float* src = g_ent;
        unsigned dst = es_u0 + (unsigned)tid * 16u;
        #pragma unroll
        for (int i = 0; i < 16; i++)
            cp16(dst + (unsigned)i * (TPB * 16u), src + (i * TPB + tid) * 4);
        cp_commit();
    }

    // ---- load all see's into smem (8KB) ----
    #pragma unroll
    for (int i = 0; i < 8; i++) sees[i * TPB + tid] = g_see[i * TPB + tid];

    // ---- load x tile, transposed ----
    #pragma unroll
    for (int i = 0; i < 32; i++) {
        int e = i * TPB + tid;
        int r = e >> 6, d = e & 63;
        xs[d * XSS + r] = x[(rowbase + r) * 64 + d];
    }
    __syncthreads();

    // ---- normalize rows (one thread per row) ----
    if (tid < RPB) {
        float s = 0.f;
        #pragma unroll
        for (int d = 0; d < 64; d++) { float v = xs[d * XSS + tid]; s += v * v; }
        float inv = 1.0f / fmaxf(sqrtf(s), 1e-12f);
        #pragma unroll
        for (int d = 0; d < 64; d++) xs[d * XSS + tid] *= inv;
    }
    // (sync before first compute happens inside the chunk loop)

    float minv[8], minkf[8], kf0[8];
    #pragma unroll
    for (int j = 0; j < 8; j++) { minv[j] = 3.4e38f; minkf[j] = 0.f; }
    #pragma unroll
    for (int p = 0; p < 8; p++) kf0[p] = (float)(2 * (tx + 16 * p));
    const ull M2 = dup2(-2.0f);
    float chbase = 0.f;

    for (int ch = 0; ch < NCH; ch++) {
        if (ch + 1 < NCH) {
            const float* src = g_ent + (ch + 1) * (64 * CPC);
            unsigned dst = (((ch + 1) & 1) ? es_u1 : es_u0) + (unsigned)tid * 16u;
            #pragma unroll
            for (int i = 0; i < 16; i++)
                cp16(dst + (unsigned)i * (TPB * 16u), src + (i * TPB + tid) * 4);
            cp_commit();
            cp_wait<1>();     // chunk ch has landed
        } else {
            cp_wait<0>();
        }
        __syncthreads();

        const ull* eb = (const ull*)((ch & 1) ? es1 : es0);

        ull acc[8][8];
        #pragma unroll
        for (int j = 0; j < 8; j++)
            #pragma unroll
            for (int p = 0; p < 8; p++) acc[j][p] = 0ull;

        #pragma unroll 4
        for (int d = 0; d < 64; d++) {
            float4 a0 = *(const float4*)(xs + d * XSS + ty * 8);
            float4 a1 = *(const float4*)(xs + d * XSS + ty * 8 + 4);
            ull A[8];
            A[0] = dup2(a0.x); A[1] = dup2(a0.y); A[2] = dup2(a0.z); A[3] = dup2(a0.w);
            A[4] = dup2(a1.x); A[5] = dup2(a1.y); A[6] = dup2(a1.z); A[7] = dup2(a1.w);
            ull B[8];
            #pragma unroll
            for (int p = 0; p < 8; p++) B[p] = eb[d * (CPC / 2) + tx + 16 * p];
            #pragma unroll
            for (int j = 0; j < 8; j++)
                #pragma unroll
                for (int p = 0; p < 8; p++)
                    acc[j][p] = fma2(A[j], B[p], acc[j][p]);
        }

        // argmin epilogue: compare v = see - 2*dot (sxx is row-constant)
        const ull* seeb = (const ull*)(sees + ch * CPC);
        #pragma unroll
        for (int p = 0; p < 8; p++) {
            ull S = seeb[tx + 16 * p];
            float klo = kf0[p] + chbase;
            #pragma unroll
            for (int j = 0; j < 8; j++) {
                ull v2 = fma2(M2, acc[j][p], S);
                float lo, hi; unpack2(v2, lo, hi);
                bool c1 = lo < minv[j];
                minv[j]  = c1 ? lo  : minv[j];
                minkf[j] = c1 ? klo : minkf[j];
                bool c2 = hi < minv[j];
                minv[j]  = c2 ? hi           : minv[j];
                minkf[j] = c2 ? (klo + 1.0f) : minkf[j];
            }
        }
        chbase += (float)CPC;
        __syncthreads();     // everyone done reading this buffer
    }

    // ---- reduce argmin across the 16 code-group threads per row ----
    float2* red = (float2*)es0;          // [RPB][16]
    #pragma unroll
    for (int j = 0; j < 8; j++)
        red[(ty * 8 + j) * 16 + tx] = make_float2(minv[j], minkf[j]);
    __syncthreads();

    float lsum = 0.f;
    if (tid < RPB) {
        float bv = 3.5e38f, bkf = 0.f;
        #pragma unroll
        for (int t = 0; t < 16; t++) {
            float2 e2 = red[tid * 16 + t];
            if (e2.x < bv || (e2.x == bv && e2.y < bkf)) { bv = e2.x; bkf = e2.y; }
        }
        int bk = (int)bkf;
        // reference re-normalizes the gathered code (idempotent, replicated)
        float inv2 = 1.0f / fmaxf(sqrtf(g_see[bk]), 1e-12f);
        const float* erow = g_en + bk * 64;
        #pragma unroll
        for (int d = 0; d < 64; d++) {
            float xnv  = xs[d * XSS + tid];
            float qd   = erow[d] * inv2;
            float diff = qd - xnv;
            lsum += diff * diff;
            xs[d * XSS + tid] = xnv + diff;      // quantized_st
        }
        if (out_size >= N_ * D_ + 1 + N_)
            out[N_ * D_ + 1 + rowbase + tid] = bkf;
    }
    __syncthreads();

    // ---- coalesced store of quantized_st tile ----
    #pragma unroll
    for (int i = 0; i < 32; i++) {
        int e = i * TPB + tid;
        out[rowbase * 64 + e] = xs[(e & 63) * XSS + (e >> 6)];
    }

    // ---- deterministic block loss reduction (reuse sees) ----
    if (tid < RPB) sees[tid] = lsum;
    __syncthreads();
    for (int s = 64; s > 0; s >>= 1) {
        if (tid < s) sees[tid] += sees[tid + s];
        __syncthreads();
    }
    if (tid == 0) g_part[blockIdx.x] = sees[0];
}

// ---------------------------------------------------------------------------
// Kernel 3: deterministic final loss reduction.
// loss = q_latent + 0.25*e_latent = 1.25 * mean((q - xn)^2)
// ---------------------------------------------------------------------------
__global__ void vq_final(float* __restrict__ out, int out_size) {
    __shared__ float sm[256];
    int tid = threadIdx.x;
    float s = g_part[tid] + g_part[tid + 256] + g_part[tid + 512] + g_part[tid + 768];
    sm[tid] = s;
    __syncthreads();
    for (int st = 128; st > 0; st >>= 1) {
        if (tid < st) sm[tid] += sm[tid + st];
        __syncthreads();
    }
    if (tid == 0 && out_size > N_ * D_)
        out[N_ * D_] = 1.25f * (sm[0] / (float)(N_ * D_));
}

// ---------------------------------------------------------------------------
extern "C" void kernel_launch(void* const* d_in, const int* in_sizes, int n_in,
                              void* d_out, int out_size) {
    const float* x;
    const float* emb;
    if (n_in >= 2 && in_sizes[0] >= in_sizes[1]) {
        x = (const float*)d_in[0]; emb = (const float*)d_in[1];
    } else {
        x = (const float*)d_in[1]; emb = (const float*)d_in[0];
    }

    const size_t dynsmem = (size_t)(64 * XSS + 2 * 64 * CPC + K_) * sizeof(float);
    cudaFuncSetAttribute(vq_main, cudaFuncAttributeMaxDynamicSharedMemorySize,
                         (int)dynsmem);

    vq_norm_emb<<<K_ / 8, 256>>>(emb);
    vq_main<<<GRID, TPB, dynsmem>>>(x, (float*)d_out, out_size);
    vq_final<<<1, 256>>>((float*)d_out, out_size);
}